// round 1
// baseline (speedup 1.0000x reference)
#include <cuda_runtime.h>
#include <math.h>

#define Bsz 8
#define Nn  1024
#define Dd  512
#define Hh  8
#define HD  64
#define Mrows (Bsz*Nn)

// Scratch (device globals: allocation-guard safe)
__device__ float g_q[Bsz*Hh*Nn*HD];
__device__ float g_k[Bsz*Hh*Nn*HD];
__device__ float g_v[Bsz*Hh*Nn*HD];
__device__ float g_attn[(size_t)Mrows*Dd];
__device__ float g_y[(size_t)Mrows*Dd];

// ---------------------------------------------------------------------------
// SGEMM: C[M=8192, 512] = A @ W^T (+bias) (+resid)
// mode 0: write to [B,H,N,HD] layout (QKV).  mode 1: plain + residual.
// Block tile 128x64, 256 threads (16x16), 8x4 microtile, k-tile 16.
// ---------------------------------------------------------------------------
__global__ __launch_bounds__(256) void gemm_kernel(
    const float* __restrict__ A, const float* __restrict__ W,
    const float* __restrict__ bias, const float* __restrict__ resid,
    float* __restrict__ out, int mode)
{
    __shared__ float As[16][128];
    __shared__ float Ws[16][64];

    const int t   = threadIdx.x;
    const int tx  = t & 15;
    const int ty  = t >> 4;
    const int row0 = blockIdx.x * 128;
    const int col0 = blockIdx.y * 64;

    float acc[8][4];
#pragma unroll
    for (int i = 0; i < 8; i++)
#pragma unroll
        for (int j = 0; j < 4; j++) acc[i][j] = 0.f;

    const int arow = t >> 1;          // 0..127
    const int ak0  = (t & 1) * 8;     // 0 or 8
    const int wn   = t >> 2;          // 0..63
    const int wk0  = (t & 3) * 4;     // 0,4,8,12

    const float* Aptr = A + (size_t)(row0 + arow) * Dd + ak0;
    const float* Wptr = W + (size_t)(col0 + wn)  * Dd + wk0;

    for (int k0 = 0; k0 < Dd; k0 += 16) {
        float4 a0 = *(const float4*)(Aptr + k0);
        float4 a1 = *(const float4*)(Aptr + k0 + 4);
        float4 w0 = *(const float4*)(Wptr + k0);
        As[ak0+0][arow] = a0.x; As[ak0+1][arow] = a0.y;
        As[ak0+2][arow] = a0.z; As[ak0+3][arow] = a0.w;
        As[ak0+4][arow] = a1.x; As[ak0+5][arow] = a1.y;
        As[ak0+6][arow] = a1.z; As[ak0+7][arow] = a1.w;
        Ws[wk0+0][wn] = w0.x; Ws[wk0+1][wn] = w0.y;
        Ws[wk0+2][wn] = w0.z; Ws[wk0+3][wn] = w0.w;
        __syncthreads();

#pragma unroll
        for (int k = 0; k < 16; k++) {
            float4 aA = *(const float4*)&As[k][ty*8];
            float4 aB = *(const float4*)&As[k][ty*8 + 4];
            float4 wv = *(const float4*)&Ws[k][tx*4];
            float av[8] = {aA.x, aA.y, aA.z, aA.w, aB.x, aB.y, aB.z, aB.w};
            float wr[4] = {wv.x, wv.y, wv.z, wv.w};
#pragma unroll
            for (int i = 0; i < 8; i++)
#pragma unroll
                for (int j = 0; j < 4; j++)
                    acc[i][j] = fmaf(av[i], wr[j], acc[i][j]);
        }
        __syncthreads();
    }

    float bb[4];
#pragma unroll
    for (int j = 0; j < 4; j++) bb[j] = bias[col0 + tx*4 + j];

    if (mode == 0) {
        const int h = col0 >> 6;  // col0 is a multiple of 64
#pragma unroll
        for (int i = 0; i < 8; i++) {
            int gr = row0 + ty*8 + i;
            int bidx = gr >> 10;
            int nidx = gr & 1023;
            float4 r;
            r.x = acc[i][0] + bb[0]; r.y = acc[i][1] + bb[1];
            r.z = acc[i][2] + bb[2]; r.w = acc[i][3] + bb[3];
            *(float4*)(out + ((size_t)(bidx*Hh + h)*Nn + nidx)*HD + tx*4) = r;
        }
    } else {
#pragma unroll
        for (int i = 0; i < 8; i++) {
            int gr = row0 + ty*8 + i;
            size_t off = (size_t)gr*Dd + col0 + tx*4;
            float4 x4 = *(const float4*)(resid + off);
            float4 r;
            r.x = acc[i][0] + bb[0] + x4.x; r.y = acc[i][1] + bb[1] + x4.y;
            r.z = acc[i][2] + bb[2] + x4.z; r.w = acc[i][3] + bb[3] + x4.w;
            *(float4*)(out + off) = r;
        }
    }
}

// ---------------------------------------------------------------------------
// Flash-style masked attention. Block = (q-tile of 64, h, b). 256 threads.
// S = (Q K^T) * scale * adj; online softmax; O = P V; write [B,N,D] layout.
// ---------------------------------------------------------------------------
#define PADW 68
#define ATTN_SMEM (4 * 64 * PADW * (int)sizeof(float))

__global__ __launch_bounds__(256) void attn_kernel(const float* __restrict__ adj)
{
    extern __shared__ float sm[];
    float* Qt = sm;                  // [k][r], 64 x 68
    float* Kt = sm + 64*PADW;        // [k][c]
    float* Vs = sm + 2*64*PADW;      // [key][d]
    float* Ps = sm + 3*64*PADW;      // [r][key]

    const int t  = threadIdx.x;
    const int tx = t & 15;
    const int ty = t >> 4;
    const int q0 = blockIdx.x * 64;
    const int h  = blockIdx.y;
    const int b  = blockIdx.z;

    const float* Qg = g_q + ((size_t)(b*Hh + h)*Nn)*HD;
    const float* Kg = g_k + ((size_t)(b*Hh + h)*Nn)*HD;
    const float* Vg = g_v + ((size_t)(b*Hh + h)*Nn)*HD;

    const int lr = t >> 2;          // 0..63
    const int lk = (t & 3) * 16;    // 0,16,32,48

    // Load Q tile transposed: Qt[k][r]
#pragma unroll
    for (int u = 0; u < 4; u++) {
        float4 qv = *(const float4*)(Qg + (size_t)(q0+lr)*HD + lk + u*4);
        Qt[(lk+u*4+0)*PADW + lr] = qv.x;
        Qt[(lk+u*4+1)*PADW + lr] = qv.y;
        Qt[(lk+u*4+2)*PADW + lr] = qv.z;
        Qt[(lk+u*4+3)*PADW + lr] = qv.w;
    }

    float o[4][4];
    float mrow[4], lrow[4];
#pragma unroll
    for (int i = 0; i < 4; i++) {
        mrow[i] = -INFINITY; lrow[i] = 0.f;
#pragma unroll
        for (int j = 0; j < 4; j++) o[i][j] = 0.f;
    }
    const float scale = 0.125f;  // 1/sqrt(64)

    for (int kt = 0; kt < Nn/64; kt++) {
        const int k0 = kt * 64;
        __syncthreads();  // protect Kt/Vs/Ps from previous iteration consumers
#pragma unroll
        for (int u = 0; u < 4; u++) {
            float4 kv = *(const float4*)(Kg + (size_t)(k0+lr)*HD + lk + u*4);
            Kt[(lk+u*4+0)*PADW + lr] = kv.x;
            Kt[(lk+u*4+1)*PADW + lr] = kv.y;
            Kt[(lk+u*4+2)*PADW + lr] = kv.z;
            Kt[(lk+u*4+3)*PADW + lr] = kv.w;
            float4 vv = *(const float4*)(Vg + (size_t)(k0+lr)*HD + lk + u*4);
            *(float4*)(Vs + lr*PADW + lk + u*4) = vv;
        }
        __syncthreads();

        // S = Q K^T over the tile
        float s[4][4];
#pragma unroll
        for (int i = 0; i < 4; i++)
#pragma unroll
            for (int j = 0; j < 4; j++) s[i][j] = 0.f;
#pragma unroll
        for (int k = 0; k < 64; k++) {
            float4 q4 = *(const float4*)(Qt + k*PADW + ty*4);
            float4 k4 = *(const float4*)(Kt + k*PADW + tx*4);
            float qv[4] = {q4.x, q4.y, q4.z, q4.w};
            float kv[4] = {k4.x, k4.y, k4.z, k4.w};
#pragma unroll
            for (int i = 0; i < 4; i++)
#pragma unroll
                for (int j = 0; j < 4; j++)
                    s[i][j] = fmaf(qv[i], kv[j], s[i][j]);
        }

        // scale + multiplicative mask, then online softmax
#pragma unroll
        for (int i = 0; i < 4; i++) {
            const int qr = q0 + ty*4 + i;
            float4 a4 = *(const float4*)(adj + ((size_t)b*Nn + qr)*Nn + k0 + tx*4);
            s[i][0] = s[i][0] * scale * a4.x;
            s[i][1] = s[i][1] * scale * a4.y;
            s[i][2] = s[i][2] * scale * a4.z;
            s[i][3] = s[i][3] * scale * a4.w;

            float mt = fmaxf(fmaxf(s[i][0], s[i][1]), fmaxf(s[i][2], s[i][3]));
            mt = fmaxf(mt, __shfl_xor_sync(0xffffffffu, mt, 1, 16));
            mt = fmaxf(mt, __shfl_xor_sync(0xffffffffu, mt, 2, 16));
            mt = fmaxf(mt, __shfl_xor_sync(0xffffffffu, mt, 4, 16));
            mt = fmaxf(mt, __shfl_xor_sync(0xffffffffu, mt, 8, 16));

            float mnew  = fmaxf(mrow[i], mt);
            float alpha = __expf(mrow[i] - mnew);
            mrow[i] = mnew;

            float ps = 0.f;
#pragma unroll
            for (int j = 0; j < 4; j++) {
                s[i][j] = __expf(s[i][j] - mnew);
                ps += s[i][j];
            }
            ps += __shfl_xor_sync(0xffffffffu, ps, 1, 16);
            ps += __shfl_xor_sync(0xffffffffu, ps, 2, 16);
            ps += __shfl_xor_sync(0xffffffffu, ps, 4, 16);
            ps += __shfl_xor_sync(0xffffffffu, ps, 8, 16);
            lrow[i] = lrow[i] * alpha + ps;
#pragma unroll
            for (int j = 0; j < 4; j++) o[i][j] *= alpha;

            float4 pw = make_float4(s[i][0], s[i][1], s[i][2], s[i][3]);
            *(float4*)(Ps + (ty*4 + i)*PADW + tx*4) = pw;
        }
        __syncthreads();

        // O += P V
#pragma unroll
        for (int kk = 0; kk < 64; kk++) {
            float4 v4 = *(const float4*)(Vs + kk*PADW + tx*4);
#pragma unroll
            for (int i = 0; i < 4; i++) {
                float p = Ps[(ty*4 + i)*PADW + kk];
                o[i][0] = fmaf(p, v4.x, o[i][0]);
                o[i][1] = fmaf(p, v4.y, o[i][1]);
                o[i][2] = fmaf(p, v4.z, o[i][2]);
                o[i][3] = fmaf(p, v4.w, o[i][3]);
            }
        }
    }

    // normalize and write [B, N, D] (d = h*64 + tx*4+j)
#pragma unroll
    for (int i = 0; i < 4; i++) {
        const float inv = 1.0f / lrow[i];
        const int qr = q0 + ty*4 + i;
        float4 r = make_float4(o[i][0]*inv, o[i][1]*inv, o[i][2]*inv, o[i][3]*inv);
        *(float4*)(g_attn + ((size_t)b*Nn + qr)*Dd + h*HD + tx*4) = r;
    }
}

// ---------------------------------------------------------------------------
// LayerNorm over last dim (512). One block (128 thr) per row.
// ---------------------------------------------------------------------------
__global__ __launch_bounds__(128) void ln_kernel(
    const float* __restrict__ gamma, const float* __restrict__ beta,
    float* __restrict__ out)
{
    const int row = blockIdx.x;
    const int t   = threadIdx.x;
    const float* y = g_y + (size_t)row * Dd;

    float4 v = *(const float4*)(y + t*4);
    float s  = v.x + v.y + v.z + v.w;
    float ss = v.x*v.x + v.y*v.y + v.z*v.z + v.w*v.w;
#pragma unroll
    for (int off = 16; off; off >>= 1) {
        s  += __shfl_xor_sync(0xffffffffu, s,  off);
        ss += __shfl_xor_sync(0xffffffffu, ss, off);
    }
    __shared__ float sbuf[8];
    const int w = t >> 5;
    if ((t & 31) == 0) { sbuf[w] = s; sbuf[4 + w] = ss; }
    __syncthreads();
    s  = sbuf[0] + sbuf[1] + sbuf[2] + sbuf[3];
    ss = sbuf[4] + sbuf[5] + sbuf[6] + sbuf[7];

    const float mean = s * (1.f/512.f);
    const float var  = ss * (1.f/512.f) - mean*mean;
    const float inv  = rsqrtf(var + 1e-5f);

    float4 g4 = *(const float4*)(gamma + t*4);
    float4 b4 = *(const float4*)(beta  + t*4);
    float4 r;
    r.x = (v.x - mean) * inv * g4.x + b4.x;
    r.y = (v.y - mean) * inv * g4.y + b4.y;
    r.z = (v.z - mean) * inv * g4.z + b4.z;
    r.w = (v.w - mean) * inv * g4.w + b4.w;
    *(float4*)(out + (size_t)row*Dd + t*4) = r;
}

// ---------------------------------------------------------------------------
extern "C" void kernel_launch(void* const* d_in, const int* in_sizes, int n_in,
                              void* d_out, int out_size)
{
    const float* X     = (const float*)d_in[0];
    const float* adj   = (const float*)d_in[1];
    const float* Wq    = (const float*)d_in[2];
    const float* bq    = (const float*)d_in[3];
    const float* Wk    = (const float*)d_in[4];
    const float* bk    = (const float*)d_in[5];
    const float* Wv    = (const float*)d_in[6];
    const float* bv    = (const float*)d_in[7];
    const float* Wo    = (const float*)d_in[8];
    const float* bo    = (const float*)d_in[9];
    const float* gamma = (const float*)d_in[10];
    const float* beta  = (const float*)d_in[11];

    float *q, *k, *v, *attn, *y;
    cudaGetSymbolAddress((void**)&q,    g_q);
    cudaGetSymbolAddress((void**)&k,    g_k);
    cudaGetSymbolAddress((void**)&v,    g_v);
    cudaGetSymbolAddress((void**)&attn, g_attn);
    cudaGetSymbolAddress((void**)&y,    g_y);

    cudaFuncSetAttribute(attn_kernel,
                         cudaFuncAttributeMaxDynamicSharedMemorySize, ATTN_SMEM);

    dim3 ggrid(Mrows/128, Dd/64);
    gemm_kernel<<<ggrid, 256>>>(X, Wq, bq, nullptr, q, 0);
    gemm_kernel<<<ggrid, 256>>>(X, Wk, bk, nullptr, k, 0);
    gemm_kernel<<<ggrid, 256>>>(X, Wv, bv, nullptr, v, 0);

    attn_kernel<<<dim3(Nn/64, Hh, Bsz), 256, ATTN_SMEM>>>(adj);

    gemm_kernel<<<ggrid, 256>>>(attn, Wo, bo, X, y, 1);

    ln_kernel<<<Mrows, 128>>>(gamma, beta, (float*)d_out);
}

// round 3
// speedup vs baseline: 1.2608x; 1.2608x over previous
#include <cuda_runtime.h>
#include <cuda_bf16.h>
#include <math.h>
#include <stdint.h>

#define Bsz 8
#define Nn  1024
#define Dd  512
#define Hh  8
#define HD  64
#define Mrows (Bsz*Nn)

// Scratch (device globals: allocation-guard safe)
__device__ float g_q[Bsz*Hh*Nn*HD];
__device__ float g_k[Bsz*Hh*Nn*HD];
__device__ float g_v[Bsz*Hh*Nn*HD];
__device__ float g_attn[(size_t)Mrows*Dd];
__device__ float g_y[(size_t)Mrows*Dd];

// ===========================================================================
// bf16-split GEMM via mma.sync.m16n8k16 (sm_80+ path, works at compute_100).
// C[8192,512] = A @ W^T (+bias)(+resid), 3 passes: hi*hi + hi*lo + lo*hi.
// CTA tile 128x128, 8 warps (2x4), warp tile 64x32. K staged 64, dbl-buffered.
// mode 0: scatter into [B,H,N,HD].  mode 1: row-major + residual.
// ===========================================================================
#define APAD2 36                      // bf162 per row (72 bf16 = 144B): conflict-free frags
#define TILE_U32 (128*APAD2)          // 4608 u32 per tile
#define GEMM_SMEM (2*4*TILE_U32*4)    // 147456 bytes

#define MMA_BF16(c0,c1,c2,c3, a0,a1,a2,a3, b0,b1) \
    asm volatile("mma.sync.aligned.m16n8k16.row.col.f32.bf16.bf16.f32 " \
        "{%0,%1,%2,%3},{%4,%5,%6,%7},{%8,%9},{%0,%1,%2,%3};" \
        : "+f"(c0),"+f"(c1),"+f"(c2),"+f"(c3) \
        : "r"(a0),"r"(a1),"r"(a2),"r"(a3),"r"(b0),"r"(b1))

__device__ __forceinline__ uint32_t pack_hi(float x, float y) {
    __nv_bfloat162 p;
    p.x = __float2bfloat16(x);
    p.y = __float2bfloat16(y);
    return *(uint32_t*)&p;
}
__device__ __forceinline__ uint32_t pack_lo(float x, float y) {
    __nv_bfloat16 hx = __float2bfloat16(x);
    __nv_bfloat16 hy = __float2bfloat16(y);
    __nv_bfloat162 p;
    p.x = __float2bfloat16(x - __bfloat162float(hx));
    p.y = __float2bfloat16(y - __bfloat162float(hy));
    return *(uint32_t*)&p;
}

__device__ __forceinline__ void gemm_fill(
    uint32_t* smem_u32, int stage,
    const float* __restrict__ A, const float* __restrict__ W,
    int row0, int col0, int k0, int t)
{
    uint32_t* base = smem_u32 + stage * 4 * TILE_U32;
    uint32_t* Ahi = base;
    uint32_t* Alo = base + TILE_U32;
    uint32_t* Bhi = base + 2*TILE_U32;
    uint32_t* Blo = base + 3*TILE_U32;

    const int r  = t >> 1;           // 0..127
    const int c0 = (t & 1) * 32;     // fp32 col offset within 64-wide stage
    const float* Ap = A + (size_t)(row0 + r) * Dd + k0 + c0;
    const float* Wp = W + (size_t)(col0 + r) * Dd + k0 + c0;
    const int ib = r * APAD2 + (c0 >> 1);
#pragma unroll
    for (int u = 0; u < 8; u++) {
        float4 a = *(const float4*)(Ap + u*4);
        float4 w = *(const float4*)(Wp + u*4);
        Ahi[ib + u*2    ] = pack_hi(a.x, a.y);
        Ahi[ib + u*2 + 1] = pack_hi(a.z, a.w);
        Alo[ib + u*2    ] = pack_lo(a.x, a.y);
        Alo[ib + u*2 + 1] = pack_lo(a.z, a.w);
        Bhi[ib + u*2    ] = pack_hi(w.x, w.y);
        Bhi[ib + u*2 + 1] = pack_hi(w.z, w.w);
        Blo[ib + u*2    ] = pack_lo(w.x, w.y);
        Blo[ib + u*2 + 1] = pack_lo(w.z, w.w);
    }
}

__global__ __launch_bounds__(256, 1) void gemm_tc(
    const float* __restrict__ A, const float* __restrict__ W,
    const float* __restrict__ bias, const float* __restrict__ resid,
    float* __restrict__ out, int mode)
{
    extern __shared__ uint32_t smu[];
    const int t = threadIdx.x;
    const int lane = t & 31, wid = t >> 5;
    const int row0 = blockIdx.x * 128, col0 = blockIdx.y * 128;
    const int wm = wid & 1, wn = wid >> 1;       // 2 x 4 warp grid
    const int g = lane >> 2, tig = lane & 3;

    float acc[4][4][4];
#pragma unroll
    for (int mt = 0; mt < 4; mt++)
#pragma unroll
        for (int nt = 0; nt < 4; nt++)
#pragma unroll
            for (int e = 0; e < 4; e++) acc[mt][nt][e] = 0.f;

    gemm_fill(smu, 0, A, W, row0, col0, 0, t);
    __syncthreads();

    for (int kt = 0; kt < 8; kt++) {
        if (kt < 7) gemm_fill(smu, (kt + 1) & 1, A, W, row0, col0, (kt + 1) * 64, t);

        const uint32_t* base = smu + (kt & 1) * 4 * TILE_U32;
        const uint32_t* Ahi = base;
        const uint32_t* Alo = base + TILE_U32;
        const uint32_t* Bhi = base + 2*TILE_U32;
        const uint32_t* Blo = base + 3*TILE_U32;

#pragma unroll
        for (int ks = 0; ks < 4; ks++) {
            const int kb = ks * 8;   // bf162 offset per K=16 step
            uint32_t ah[4][4], al[4][4], bh[4][2], bl[4][2];
#pragma unroll
            for (int mt = 0; mt < 4; mt++) {
                const int r0 = wm*64 + mt*16 + g;
                ah[mt][0] = Ahi[ r0     *APAD2 + kb + tig];
                ah[mt][1] = Ahi[(r0 + 8)*APAD2 + kb + tig];
                ah[mt][2] = Ahi[ r0     *APAD2 + kb + tig + 4];
                ah[mt][3] = Ahi[(r0 + 8)*APAD2 + kb + tig + 4];
                al[mt][0] = Alo[ r0     *APAD2 + kb + tig];
                al[mt][1] = Alo[(r0 + 8)*APAD2 + kb + tig];
                al[mt][2] = Alo[ r0     *APAD2 + kb + tig + 4];
                al[mt][3] = Alo[(r0 + 8)*APAD2 + kb + tig + 4];
            }
#pragma unroll
            for (int nt = 0; nt < 4; nt++) {
                const int n0 = wn*32 + nt*8 + g;
                bh[nt][0] = Bhi[n0*APAD2 + kb + tig];
                bh[nt][1] = Bhi[n0*APAD2 + kb + tig + 4];
                bl[nt][0] = Blo[n0*APAD2 + kb + tig];
                bl[nt][1] = Blo[n0*APAD2 + kb + tig + 4];
            }
#pragma unroll
            for (int mt = 0; mt < 4; mt++)
#pragma unroll
                for (int nt = 0; nt < 4; nt++) {
                    MMA_BF16(acc[mt][nt][0],acc[mt][nt][1],acc[mt][nt][2],acc[mt][nt][3],
                             ah[mt][0],ah[mt][1],ah[mt][2],ah[mt][3], bh[nt][0],bh[nt][1]);
                    MMA_BF16(acc[mt][nt][0],acc[mt][nt][1],acc[mt][nt][2],acc[mt][nt][3],
                             ah[mt][0],ah[mt][1],ah[mt][2],ah[mt][3], bl[nt][0],bl[nt][1]);
                    MMA_BF16(acc[mt][nt][0],acc[mt][nt][1],acc[mt][nt][2],acc[mt][nt][3],
                             al[mt][0],al[mt][1],al[mt][2],al[mt][3], bh[nt][0],bh[nt][1]);
                }
        }
        __syncthreads();
    }

    // Epilogue
#pragma unroll
    for (int mt = 0; mt < 4; mt++) {
#pragma unroll
        for (int nt = 0; nt < 4; nt++) {
            const int gc = col0 + wn*32 + nt*8 + tig*2;
            const float b0 = bias[gc], b1 = bias[gc+1];
            const int ra = row0 + wm*64 + mt*16 + g;
            const int rb = ra + 8;
            if (mode == 0) {
                const int h = gc >> 6, d = gc & 63;
                {
                    const int bi = ra >> 10, ni = ra & 1023;
                    float2 r; r.x = acc[mt][nt][0] + b0; r.y = acc[mt][nt][1] + b1;
                    *(float2*)(out + ((size_t)(bi*Hh + h)*Nn + ni)*HD + d) = r;
                }
                {
                    const int bi = rb >> 10, ni = rb & 1023;
                    float2 r; r.x = acc[mt][nt][2] + b0; r.y = acc[mt][nt][3] + b1;
                    *(float2*)(out + ((size_t)(bi*Hh + h)*Nn + ni)*HD + d) = r;
                }
            } else {
                {
                    const size_t off = (size_t)ra * Dd + gc;
                    float2 x = *(const float2*)(resid + off);
                    float2 r; r.x = acc[mt][nt][0] + b0 + x.x; r.y = acc[mt][nt][1] + b1 + x.y;
                    *(float2*)(out + off) = r;
                }
                {
                    const size_t off = (size_t)rb * Dd + gc;
                    float2 x = *(const float2*)(resid + off);
                    float2 r; r.x = acc[mt][nt][2] + b0 + x.x; r.y = acc[mt][nt][3] + b1 + x.y;
                    *(float2*)(out + off) = r;
                }
            }
        }
    }
}

// ===========================================================================
// Flash-style masked attention, 128q x 128k tiles, 8x8 S microtile (FFMA).
// Keys per thread: {tx*4+j, 64+tx*4+j} -> all LDS.128 at 16B lane stride.
// ===========================================================================
#define QP 132   // padded row width for Qt/Kt/Ps
#define VP 68
// floats: Qt 64*132, Kt 64*132, Vs 128*68, Ps 128*132
#define OFF_KT (64*QP)
#define OFF_VS (2*64*QP)
#define OFF_PS (2*64*QP + 128*VP)
#define ATTN_SMEM ((2*64*QP + 128*VP + 128*QP) * (int)sizeof(float))  // 169984

__global__ __launch_bounds__(256, 1) void attn_kernel(const float* __restrict__ adj)
{
    extern __shared__ float smf[];
    float* Qt = smf;            // [k][q]   64 x 132
    float* Kt = smf + OFF_KT;   // [k][key] 64 x 132
    float* Vs = smf + OFF_VS;   // [key][d] 128 x 68
    float* Ps = smf + OFF_PS;   // [q][key] 128 x 132

    const int t  = threadIdx.x;
    const int tx = t & 15;
    const int ty = t >> 4;
    const int q0 = blockIdx.x * 128;
    const int h  = blockIdx.y;
    const int b  = blockIdx.z;

    const float* Qg = g_q + ((size_t)(b*Hh + h)*Nn)*HD;
    const float* Kg = g_k + ((size_t)(b*Hh + h)*Nn)*HD;
    const float* Vg = g_v + ((size_t)(b*Hh + h)*Nn)*HD;

    const int lr = t >> 1;          // 0..127
    const int lc = (t & 1) * 32;    // 0 / 32

    // Q tile transposed: Qt[k][q]
#pragma unroll
    for (int u = 0; u < 8; u++) {
        float4 qv = *(const float4*)(Qg + (size_t)(q0+lr)*HD + lc + u*4);
        Qt[(lc+u*4+0)*QP + lr] = qv.x;
        Qt[(lc+u*4+1)*QP + lr] = qv.y;
        Qt[(lc+u*4+2)*QP + lr] = qv.z;
        Qt[(lc+u*4+3)*QP + lr] = qv.w;
    }

    float o[8][4];
    float mrow[8], lrow[8];
#pragma unroll
    for (int i = 0; i < 8; i++) {
        mrow[i] = -INFINITY; lrow[i] = 0.f;
#pragma unroll
        for (int j = 0; j < 4; j++) o[i][j] = 0.f;
    }
    const float scale = 0.125f;   // 1/sqrt(64)

    for (int kt = 0; kt < Nn/128; kt++) {
        const int k0 = kt * 128;
        __syncthreads();   // prior consumers done (also covers Q fill on kt=0)
        // K tile transposed + V tile direct
#pragma unroll
        for (int u = 0; u < 8; u++) {
            float4 kv = *(const float4*)(Kg + (size_t)(k0+lr)*HD + lc + u*4);
            Kt[(lc+u*4+0)*QP + lr] = kv.x;
            Kt[(lc+u*4+1)*QP + lr] = kv.y;
            Kt[(lc+u*4+2)*QP + lr] = kv.z;
            Kt[(lc+u*4+3)*QP + lr] = kv.w;
            float4 vv = *(const float4*)(Vg + (size_t)(k0+lr)*HD + lc + u*4);
            *(float4*)(Vs + lr*VP + lc + u*4) = vv;
        }
        __syncthreads();

        // S = Q K^T : 8 queries (ty*8+i) x 8 keys ({tx*4+j, 64+tx*4+j})
        float s[8][8];
#pragma unroll
        for (int i = 0; i < 8; i++)
#pragma unroll
            for (int j = 0; j < 8; j++) s[i][j] = 0.f;
#pragma unroll
        for (int k = 0; k < 64; k++) {
            float4 qa = *(const float4*)(Qt + k*QP + ty*8);
            float4 qb = *(const float4*)(Qt + k*QP + ty*8 + 4);
            float4 ka = *(const float4*)(Kt + k*QP + tx*4);
            float4 kb = *(const float4*)(Kt + k*QP + 64 + tx*4);
            float qv[8] = {qa.x,qa.y,qa.z,qa.w, qb.x,qb.y,qb.z,qb.w};
            float kv[8] = {ka.x,ka.y,ka.z,ka.w, kb.x,kb.y,kb.z,kb.w};
#pragma unroll
            for (int i = 0; i < 8; i++)
#pragma unroll
                for (int j = 0; j < 8; j++)
                    s[i][j] = fmaf(qv[i], kv[j], s[i][j]);
        }

        // scale + multiplicative adjacency, online softmax
#pragma unroll
        for (int i = 0; i < 8; i++) {
            const int qr = q0 + ty*8 + i;
            const float* arow = adj + ((size_t)b*Nn + qr)*Nn + k0;
            float4 aa = *(const float4*)(arow + tx*4);
            float4 ab = *(const float4*)(arow + 64 + tx*4);
            s[i][0] *= scale * aa.x;  s[i][1] *= scale * aa.y;
            s[i][2] *= scale * aa.z;  s[i][3] *= scale * aa.w;
            s[i][4] *= scale * ab.x;  s[i][5] *= scale * ab.y;
            s[i][6] *= scale * ab.z;  s[i][7] *= scale * ab.w;

            float mt4 = s[i][0];
#pragma unroll
            for (int j = 1; j < 8; j++) mt4 = fmaxf(mt4, s[i][j]);
            mt4 = fmaxf(mt4, __shfl_xor_sync(0xffffffffu, mt4, 1, 16));
            mt4 = fmaxf(mt4, __shfl_xor_sync(0xffffffffu, mt4, 2, 16));
            mt4 = fmaxf(mt4, __shfl_xor_sync(0xffffffffu, mt4, 4, 16));
            mt4 = fmaxf(mt4, __shfl_xor_sync(0xffffffffu, mt4, 8, 16));

            float mnew  = fmaxf(mrow[i], mt4);
            float alpha = __expf(mrow[i] - mnew);
            mrow[i] = mnew;

            float ps = 0.f;
#pragma unroll
            for (int j = 0; j < 8; j++) {
                s[i][j] = __expf(s[i][j] - mnew);
                ps += s[i][j];
            }
            ps += __shfl_xor_sync(0xffffffffu, ps, 1, 16);
            ps += __shfl_xor_sync(0xffffffffu, ps, 2, 16);
            ps += __shfl_xor_sync(0xffffffffu, ps, 4, 16);
            ps += __shfl_xor_sync(0xffffffffu, ps, 8, 16);
            lrow[i] = lrow[i] * alpha + ps;
#pragma unroll
            for (int j = 0; j < 4; j++) o[i][j] *= alpha;

            *(float4*)(Ps + (ty*8 + i)*QP + tx*4)      = make_float4(s[i][0],s[i][1],s[i][2],s[i][3]);
            *(float4*)(Ps + (ty*8 + i)*QP + 64 + tx*4) = make_float4(s[i][4],s[i][5],s[i][6],s[i][7]);
        }
        __syncthreads();

        // O += P V (kk unrolled by 4; p via lds.128)
#pragma unroll 4
        for (int kk = 0; kk < 128; kk += 4) {
            float4 v0 = *(const float4*)(Vs + (kk+0)*VP + tx*4);
            float4 v1 = *(const float4*)(Vs + (kk+1)*VP + tx*4);
            float4 v2 = *(const float4*)(Vs + (kk+2)*VP + tx*4);
            float4 v3 = *(const float4*)(Vs + (kk+3)*VP + tx*4);
#pragma unroll
            for (int i = 0; i < 8; i++) {
                float4 p4 = *(const float4*)(Ps + (ty*8 + i)*QP + kk);
                o[i][0] = fmaf(p4.x, v0.x, o[i][0]);
                o[i][1] = fmaf(p4.x, v0.y, o[i][1]);
                o[i][2] = fmaf(p4.x, v0.z, o[i][2]);
                o[i][3] = fmaf(p4.x, v0.w, o[i][3]);
                o[i][0] = fmaf(p4.y, v1.x, o[i][0]);
                o[i][1] = fmaf(p4.y, v1.y, o[i][1]);
                o[i][2] = fmaf(p4.y, v1.z, o[i][2]);
                o[i][3] = fmaf(p4.y, v1.w, o[i][3]);
                o[i][0] = fmaf(p4.z, v2.x, o[i][0]);
                o[i][1] = fmaf(p4.z, v2.y, o[i][1]);
                o[i][2] = fmaf(p4.z, v2.z, o[i][2]);
                o[i][3] = fmaf(p4.z, v2.w, o[i][3]);
                o[i][0] = fmaf(p4.w, v3.x, o[i][0]);
                o[i][1] = fmaf(p4.w, v3.y, o[i][1]);
                o[i][2] = fmaf(p4.w, v3.z, o[i][2]);
                o[i][3] = fmaf(p4.w, v3.w, o[i][3]);
            }
        }
    }

    // normalize and write [B, N, D] (d = h*64 + tx*4+j)
#pragma unroll
    for (int i = 0; i < 8; i++) {
        const float inv = 1.0f / lrow[i];
        const int qr = q0 + ty*8 + i;
        float4 r = make_float4(o[i][0]*inv, o[i][1]*inv, o[i][2]*inv, o[i][3]*inv);
        *(float4*)(g_attn + ((size_t)b*Nn + qr)*Dd + h*HD + tx*4) = r;
    }
}

// ---------------------------------------------------------------------------
// LayerNorm over last dim (512). One block (128 thr) per row.
// ---------------------------------------------------------------------------
__global__ __launch_bounds__(128) void ln_kernel(
    const float* __restrict__ gamma, const float* __restrict__ beta,
    float* __restrict__ out)
{
    const int row = blockIdx.x;
    const int t   = threadIdx.x;
    const float* y = g_y + (size_t)row * Dd;

    float4 v = *(const float4*)(y + t*4);
    float s  = v.x + v.y + v.z + v.w;
    float ss = v.x*v.x + v.y*v.y + v.z*v.z + v.w*v.w;
#pragma unroll
    for (int off = 16; off; off >>= 1) {
        s  += __shfl_xor_sync(0xffffffffu, s,  off);
        ss += __shfl_xor_sync(0xffffffffu, ss, off);
    }
    __shared__ float sbuf[8];
    const int w = t >> 5;
    if ((t & 31) == 0) { sbuf[w] = s; sbuf[4 + w] = ss; }
    __syncthreads();
    s  = sbuf[0] + sbuf[1] + sbuf[2] + sbuf[3];
    ss = sbuf[4] + sbuf[5] + sbuf[6] + sbuf[7];

    const float mean = s * (1.f/512.f);
    const float var  = ss * (1.f/512.f) - mean*mean;
    const float inv  = rsqrtf(var + 1e-5f);

    float4 g4 = *(const float4*)(gamma + t*4);
    float4 b4 = *(const float4*)(beta  + t*4);
    float4 r;
    r.x = (v.x - mean) * inv * g4.x + b4.x;
    r.y = (v.y - mean) * inv * g4.y + b4.y;
    r.z = (v.z - mean) * inv * g4.z + b4.z;
    r.w = (v.w - mean) * inv * g4.w + b4.w;
    *(float4*)(out + (size_t)row*Dd + t*4) = r;
}

// ---------------------------------------------------------------------------
extern "C" void kernel_launch(void* const* d_in, const int* in_sizes, int n_in,
                              void* d_out, int out_size)
{
    const float* X     = (const float*)d_in[0];
    const float* adj   = (const float*)d_in[1];
    const float* Wq    = (const float*)d_in[2];
    const float* bq    = (const float*)d_in[3];
    const float* Wk    = (const float*)d_in[4];
    const float* bk    = (const float*)d_in[5];
    const float* Wv    = (const float*)d_in[6];
    const float* bv    = (const float*)d_in[7];
    const float* Wo    = (const float*)d_in[8];
    const float* bo    = (const float*)d_in[9];
    const float* gamma = (const float*)d_in[10];
    const float* beta  = (const float*)d_in[11];

    float *q, *k, *v, *attn, *y;
    cudaGetSymbolAddress((void**)&q,    g_q);
    cudaGetSymbolAddress((void**)&k,    g_k);
    cudaGetSymbolAddress((void**)&v,    g_v);
    cudaGetSymbolAddress((void**)&attn, g_attn);
    cudaGetSymbolAddress((void**)&y,    g_y);

    cudaFuncSetAttribute(gemm_tc,
                         cudaFuncAttributeMaxDynamicSharedMemorySize, GEMM_SMEM);
    cudaFuncSetAttribute(attn_kernel,
                         cudaFuncAttributeMaxDynamicSharedMemorySize, ATTN_SMEM);

    dim3 ggrid(Mrows/128, Dd/128);
    gemm_tc<<<ggrid, 256, GEMM_SMEM>>>(X, Wq, bq, nullptr, q, 0);
    gemm_tc<<<ggrid, 256, GEMM_SMEM>>>(X, Wk, bk, nullptr, k, 0);
    gemm_tc<<<ggrid, 256, GEMM_SMEM>>>(X, Wv, bv, nullptr, v, 0);

    attn_kernel<<<dim3(Nn/128, Hh, Bsz), 256, ATTN_SMEM>>>(adj);

    gemm_tc<<<ggrid, 256, GEMM_SMEM>>>(attn, Wo, bo, X, y, 1);

    ln_kernel<<<Mrows, 128>>>(gamma, beta, (float*)d_out);
}

// round 5
// speedup vs baseline: 2.0465x; 1.6231x over previous
#include <cuda_runtime.h>
#include <cuda_bf16.h>
#include <math.h>
#include <stdint.h>

#define Bsz 8
#define Nn  1024
#define Dd  512
#define Hh  8
#define HD  64
#define Mrows (Bsz*Nn)

// ---------------- scratch (device globals) ----------------
// u32 = packed bf162 (even,odd) pairs. Row layouts noted per buffer.
__device__ uint32_t g_xhi[Mrows*256], g_xlo[Mrows*256];        // X split  [row][256]
__device__ uint32_t g_whi[4*512*256], g_wlo[4*512*256];        // 4 weights [w][row][256]
__device__ uint32_t g_qhi[Mrows*32*Hh], g_qlo[Mrows*32*Hh];    // [B,H,N][32]
__device__ uint32_t g_khi[Mrows*32*Hh], g_klo[Mrows*32*Hh];
__device__ uint32_t g_vhi[Mrows*32*Hh], g_vlo[Mrows*32*Hh];
__device__ uint32_t g_athi[Mrows*256], g_atlo[Mrows*256];      // attn out split [row][256]
__device__ float    g_y[(size_t)Mrows*Dd];

// ---------------- helpers ----------------
__device__ __forceinline__ uint32_t smem_u32(const void* p) {
    uint32_t a;
    asm("{ .reg .u64 t; cvta.to.shared.u64 t, %1; cvt.u32.u64 %0, t; }" : "=r"(a) : "l"(p));
    return a;
}
#define MMA_BF16(c0,c1,c2,c3, a0,a1,a2,a3, b0,b1) \
    asm volatile("mma.sync.aligned.m16n8k16.row.col.f32.bf16.bf16.f32 " \
        "{%0,%1,%2,%3},{%4,%5,%6,%7},{%8,%9},{%0,%1,%2,%3};" \
        : "+f"(c0),"+f"(c1),"+f"(c2),"+f"(c3) \
        : "r"(a0),"r"(a1),"r"(a2),"r"(a3),"r"(b0),"r"(b1))
#define LDSM_X4(r0,r1,r2,r3, a) \
    asm volatile("ldmatrix.sync.aligned.m8n8.x4.shared.b16 {%0,%1,%2,%3}, [%4];" \
        : "=r"(r0),"=r"(r1),"=r"(r2),"=r"(r3) : "r"(a))
#define LDSM_X4_T(r0,r1,r2,r3, a) \
    asm volatile("ldmatrix.sync.aligned.m8n8.x4.trans.shared.b16 {%0,%1,%2,%3}, [%4];" \
        : "=r"(r0),"=r"(r1),"=r"(r2),"=r"(r3) : "r"(a))

__device__ __forceinline__ uint32_t pack_hi(float x, float y) {
    __nv_bfloat162 p;
    p.x = __float2bfloat16(x);
    p.y = __float2bfloat16(y);
    return *(uint32_t*)&p;
}
__device__ __forceinline__ uint32_t pack_lo(float x, float y) {
    __nv_bfloat16 hx = __float2bfloat16(x);
    __nv_bfloat16 hy = __float2bfloat16(y);
    __nv_bfloat162 p;
    p.x = __float2bfloat16(x - __bfloat162float(hx));
    p.y = __float2bfloat16(y - __bfloat162float(hy));
    return *(uint32_t*)&p;
}

// ---------------- split convert: fp32 -> (hi,lo) bf162-packed u32 ----------------
__global__ __launch_bounds__(256) void split_kernel(
    const float* __restrict__ in, uint32_t* __restrict__ hi,
    uint32_t* __restrict__ lo, int n4)
{
    int i = blockIdx.x * 256 + threadIdx.x;
    if (i < n4) {
        float4 v = ((const float4*)in)[i];
        uint2 h, l;
        h.x = pack_hi(v.x, v.y); h.y = pack_hi(v.z, v.w);
        l.x = pack_lo(v.x, v.y); l.y = pack_lo(v.z, v.w);
        ((uint2*)hi)[i] = h;
        ((uint2*)lo)[i] = l;
    }
}

// ===========================================================================
// bf16-split GEMM (pre-split inputs). CTA 128x128, 8 warps (2x4), K-stage 64.
// mode 0: write split u32 into [B,H,N][32].  mode 1: fp32 + bias + resid.
// ===========================================================================
#define APAD2 36
#define TILE_U32 (128*APAD2)
#define GEMM_SMEM (2*4*TILE_U32*4)    // 147456 bytes

__device__ __forceinline__ void gfill(
    uint32_t* smu, int stage,
    const uint32_t* __restrict__ Ahi, const uint32_t* __restrict__ Alo,
    const uint32_t* __restrict__ Bhi, const uint32_t* __restrict__ Blo,
    int row0, int col0, int k0u, int t)
{
    const int r = t >> 1, c0 = (t & 1) * 16;
    uint32_t* d = smu + stage * 4 * TILE_U32;
    const uint32_t* s0 = Ahi + (size_t)(row0 + r) * 256 + k0u + c0;
    const uint32_t* s1 = Alo + (size_t)(row0 + r) * 256 + k0u + c0;
    const uint32_t* s2 = Bhi + (size_t)(col0 + r) * 256 + k0u + c0;
    const uint32_t* s3 = Blo + (size_t)(col0 + r) * 256 + k0u + c0;
    uint32_t* dd = d + r * APAD2 + c0;
#pragma unroll
    for (int u = 0; u < 4; u++) {
        ((uint4*)(dd             ))[u] = ((const uint4*)s0)[u];
        ((uint4*)(dd + TILE_U32  ))[u] = ((const uint4*)s1)[u];
        ((uint4*)(dd + 2*TILE_U32))[u] = ((const uint4*)s2)[u];
        ((uint4*)(dd + 3*TILE_U32))[u] = ((const uint4*)s3)[u];
    }
}

__global__ __launch_bounds__(256, 1) void gemm_tc(
    const uint32_t* __restrict__ Ahi, const uint32_t* __restrict__ Alo,
    const uint32_t* __restrict__ Bwhi, const uint32_t* __restrict__ Bwlo,
    const float* __restrict__ bias, const float* __restrict__ resid,
    float* __restrict__ outf, uint32_t* __restrict__ outhi,
    uint32_t* __restrict__ outlo, int mode)
{
    extern __shared__ uint32_t smu[];
    const int t = threadIdx.x;
    const int lane = t & 31, wid = t >> 5;
    const int row0 = blockIdx.x * 128, col0 = blockIdx.y * 128;
    const int wm = wid & 1, wn = wid >> 1;
    const int g = lane >> 2, tig = lane & 3;

    float acc[4][4][4];
#pragma unroll
    for (int mt = 0; mt < 4; mt++)
#pragma unroll
        for (int nt = 0; nt < 4; nt++)
#pragma unroll
            for (int e = 0; e < 4; e++) acc[mt][nt][e] = 0.f;

    gfill(smu, 0, Ahi, Alo, Bwhi, Bwlo, row0, col0, 0, t);
    __syncthreads();

    for (int kt = 0; kt < 8; kt++) {
        if (kt < 7) gfill(smu, (kt + 1) & 1, Ahi, Alo, Bwhi, Bwlo, row0, col0, (kt + 1) * 32, t);

        const uint32_t* base = smu + (kt & 1) * 4 * TILE_U32;
        const uint32_t* sAhi = base;
        const uint32_t* sAlo = base + TILE_U32;
        const uint32_t* sBhi = base + 2*TILE_U32;
        const uint32_t* sBlo = base + 3*TILE_U32;

#pragma unroll
        for (int ks = 0; ks < 4; ks++) {
            const int kb = ks * 8;
            uint32_t ah[4][4], al[4][4], bh[4][2], bl[4][2];
#pragma unroll
            for (int mt = 0; mt < 4; mt++) {
                const int r0 = wm*64 + mt*16 + g;
                ah[mt][0] = sAhi[ r0     *APAD2 + kb + tig];
                ah[mt][1] = sAhi[(r0 + 8)*APAD2 + kb + tig];
                ah[mt][2] = sAhi[ r0     *APAD2 + kb + tig + 4];
                ah[mt][3] = sAhi[(r0 + 8)*APAD2 + kb + tig + 4];
                al[mt][0] = sAlo[ r0     *APAD2 + kb + tig];
                al[mt][1] = sAlo[(r0 + 8)*APAD2 + kb + tig];
                al[mt][2] = sAlo[ r0     *APAD2 + kb + tig + 4];
                al[mt][3] = sAlo[(r0 + 8)*APAD2 + kb + tig + 4];
            }
#pragma unroll
            for (int nt = 0; nt < 4; nt++) {
                const int n0 = wn*32 + nt*8 + g;
                bh[nt][0] = sBhi[n0*APAD2 + kb + tig];
                bh[nt][1] = sBhi[n0*APAD2 + kb + tig + 4];
                bl[nt][0] = sBlo[n0*APAD2 + kb + tig];
                bl[nt][1] = sBlo[n0*APAD2 + kb + tig + 4];
            }
#pragma unroll
            for (int mt = 0; mt < 4; mt++)
#pragma unroll
                for (int nt = 0; nt < 4; nt++) {
                    MMA_BF16(acc[mt][nt][0],acc[mt][nt][1],acc[mt][nt][2],acc[mt][nt][3],
                             ah[mt][0],ah[mt][1],ah[mt][2],ah[mt][3], bh[nt][0],bh[nt][1]);
                    MMA_BF16(acc[mt][nt][0],acc[mt][nt][1],acc[mt][nt][2],acc[mt][nt][3],
                             ah[mt][0],ah[mt][1],ah[mt][2],ah[mt][3], bl[nt][0],bl[nt][1]);
                    MMA_BF16(acc[mt][nt][0],acc[mt][nt][1],acc[mt][nt][2],acc[mt][nt][3],
                             al[mt][0],al[mt][1],al[mt][2],al[mt][3], bh[nt][0],bh[nt][1]);
                }
        }
        __syncthreads();
    }

#pragma unroll
    for (int mt = 0; mt < 4; mt++) {
#pragma unroll
        for (int nt = 0; nt < 4; nt++) {
            const int gc = col0 + wn*32 + nt*8 + tig*2;
            const float b0 = bias[gc], b1 = bias[gc+1];
            const int ra = row0 + wm*64 + mt*16 + g;
            const int rb = ra + 8;
            if (mode == 0) {
                const int h = gc >> 6, ucol = (gc >> 1) & 31;
                {
                    const int bi = ra >> 10, ni = ra & 1023;
                    const float x = acc[mt][nt][0] + b0, y = acc[mt][nt][1] + b1;
                    const size_t o = ((size_t)(bi*Hh + h)*Nn + ni)*32 + ucol;
                    outhi[o] = pack_hi(x, y);  outlo[o] = pack_lo(x, y);
                }
                {
                    const int bi = rb >> 10, ni = rb & 1023;
                    const float x = acc[mt][nt][2] + b0, y = acc[mt][nt][3] + b1;
                    const size_t o = ((size_t)(bi*Hh + h)*Nn + ni)*32 + ucol;
                    outhi[o] = pack_hi(x, y);  outlo[o] = pack_lo(x, y);
                }
            } else {
                {
                    const size_t off = (size_t)ra * Dd + gc;
                    float2 x = *(const float2*)(resid + off);
                    float2 r; r.x = acc[mt][nt][0] + b0 + x.x; r.y = acc[mt][nt][1] + b1 + x.y;
                    *(float2*)(outf + off) = r;
                }
                {
                    const size_t off = (size_t)rb * Dd + gc;
                    float2 x = *(const float2*)(resid + off);
                    float2 r; r.x = acc[mt][nt][2] + b0 + x.x; r.y = acc[mt][nt][3] + b1 + x.y;
                    *(float2*)(outf + off) = r;
                }
            }
        }
    }
}

// ===========================================================================
// Tensor-core flash attention. CTA = 128q x (b,h); 8 warps, warp = 16q x 128k.
// S = (Qhi+Qlo)(Khi+Klo)^T via 3 mma passes; softmax in-warp; P re-packed to
// A-frags; O += P V via ldmatrix.trans B-frags, 3 passes.
// ===========================================================================
#define ASTRIDE 144                    // bytes per smem row (36 u32)
#define AT_TILE_U32 (128*36)           // one K/V tile
#define ATTN_SMEM (4*AT_TILE_U32*4)    // 73728 bytes

__global__ __launch_bounds__(256, 1) void attn_kernel(const float* __restrict__ adj)
{
    extern __shared__ uint32_t smu[];
    const uint32_t smb = smem_u32(smu);
    const int t = threadIdx.x;
    const int lane = t & 31, wid = t >> 5;
    const int g = lane >> 2, tig = lane & 3;
    const int lm = lane >> 3, lr8 = lane & 7;
    const int q0 = blockIdx.x * 128;
    const int h  = blockIdx.y;
    const int b  = blockIdx.z;

    const size_t hbase = (size_t)(b*Hh + h) * Nn * 32;
    const uint32_t* Qhi = g_qhi + hbase;
    const uint32_t* Qlo = g_qlo + hbase;
    const uint32_t* Khi = g_khi + hbase;
    const uint32_t* Klo = g_klo + hbase;
    const uint32_t* Vhi = g_vhi + hbase;
    const uint32_t* Vlo = g_vlo + hbase;

    const uint32_t smbKhi = smb;
    const uint32_t smbKlo = smb + 1*AT_TILE_U32*4;
    const uint32_t smbVhi = smb + 2*AT_TILE_U32*4;
    const uint32_t smbVlo = smb + 3*AT_TILE_U32*4;

    // ldmatrix lane offsets (bytes)
    const int lofK = ((lm >> 1)*8 + lr8) * ASTRIDE + (lm & 1) * 16;
    const int lofV = ((lm & 1)*8 + lr8) * ASTRIDE + (lm >> 1) * 16;

    // Q fragments (held in regs for the whole kernel)
    const int rq  = q0 + wid*16 + g;
    const int rq8 = rq + 8;
    uint32_t qh[4][4], ql[4][4];
#pragma unroll
    for (int ks = 0; ks < 4; ks++) {
        const int c = ks*8 + tig;
        qh[ks][0] = Qhi[(size_t)rq *32 + c];     qh[ks][1] = Qhi[(size_t)rq8*32 + c];
        qh[ks][2] = Qhi[(size_t)rq *32 + c + 4]; qh[ks][3] = Qhi[(size_t)rq8*32 + c + 4];
        ql[ks][0] = Qlo[(size_t)rq *32 + c];     ql[ks][1] = Qlo[(size_t)rq8*32 + c];
        ql[ks][2] = Qlo[(size_t)rq *32 + c + 4]; ql[ks][3] = Qlo[(size_t)rq8*32 + c + 4];
    }

    float o[8][4];
#pragma unroll
    for (int i = 0; i < 8; i++)
#pragma unroll
        for (int e = 0; e < 4; e++) o[i][e] = 0.f;
    float m0 = -INFINITY, m1 = -INFINITY, l0 = 0.f, l1 = 0.f;
    const float scale = 0.125f;

    const int fr = t >> 1, fc = (t & 1) * 16;     // fill mapping

    for (int kt = 0; kt < 8; kt++) {
        const int k0 = kt * 128;
        __syncthreads();
        // fill K/V hi/lo tiles: [key][36 u32] rows
        {
            const size_t gsrc = (size_t)(k0 + fr) * 32 + fc;
            uint32_t* d = smu + fr*36 + fc;
#pragma unroll
            for (int u = 0; u < 4; u++) {
                ((uint4*)(d                ))[u] = ((const uint4*)(Khi + gsrc))[u];
                ((uint4*)(d +   AT_TILE_U32))[u] = ((const uint4*)(Klo + gsrc))[u];
                ((uint4*)(d + 2*AT_TILE_U32))[u] = ((const uint4*)(Vhi + gsrc))[u];
                ((uint4*)(d + 3*AT_TILE_U32))[u] = ((const uint4*)(Vlo + gsrc))[u];
            }
        }
        __syncthreads();

        // ---- S = Q K^T (fp32 accum, 3 split passes) ----
        float sc[16][4];
#pragma unroll
        for (int i = 0; i < 16; i++)
#pragma unroll
            for (int e = 0; e < 4; e++) sc[i][e] = 0.f;

#pragma unroll
        for (int ks = 0; ks < 4; ks++) {
#pragma unroll
            for (int nfp = 0; nfp < 8; nfp++) {
                uint32_t kh0,kh1,kh2,kh3, kl0,kl1,kl2,kl3;
                const uint32_t aK = lofK + nfp*2304 + ks*32;
                LDSM_X4(kh0,kh1,kh2,kh3, smbKhi + aK);
                LDSM_X4(kl0,kl1,kl2,kl3, smbKlo + aK);
                float* s0 = sc[2*nfp];
                float* s1 = sc[2*nfp+1];
                MMA_BF16(s0[0],s0[1],s0[2],s0[3], qh[ks][0],qh[ks][1],qh[ks][2],qh[ks][3], kh0,kh1);
                MMA_BF16(s0[0],s0[1],s0[2],s0[3], qh[ks][0],qh[ks][1],qh[ks][2],qh[ks][3], kl0,kl1);
                MMA_BF16(s0[0],s0[1],s0[2],s0[3], ql[ks][0],ql[ks][1],ql[ks][2],ql[ks][3], kh0,kh1);
                MMA_BF16(s1[0],s1[1],s1[2],s1[3], qh[ks][0],qh[ks][1],qh[ks][2],qh[ks][3], kh2,kh3);
                MMA_BF16(s1[0],s1[1],s1[2],s1[3], qh[ks][0],qh[ks][1],qh[ks][2],qh[ks][3], kl2,kl3);
                MMA_BF16(s1[0],s1[1],s1[2],s1[3], ql[ks][0],ql[ks][1],ql[ks][2],ql[ks][3], kh2,kh3);
            }
        }

        // ---- mask + online softmax ----
        const float* arow0 = adj + ((size_t)b*Nn + rq )*Nn + k0 + 2*tig;
        const float* arow1 = adj + ((size_t)b*Nn + rq8)*Nn + k0 + 2*tig;
        float tm0 = -INFINITY, tm1 = -INFINITY;
#pragma unroll
        for (int nf = 0; nf < 16; nf++) {
            float2 a0 = *(const float2*)(arow0 + nf*8);
            float2 a1 = *(const float2*)(arow1 + nf*8);
            sc[nf][0] *= scale * a0.x;  sc[nf][1] *= scale * a0.y;
            sc[nf][2] *= scale * a1.x;  sc[nf][3] *= scale * a1.y;
            tm0 = fmaxf(tm0, fmaxf(sc[nf][0], sc[nf][1]));
            tm1 = fmaxf(tm1, fmaxf(sc[nf][2], sc[nf][3]));
        }
        tm0 = fmaxf(tm0, __shfl_xor_sync(0xffffffffu, tm0, 1, 4));
        tm0 = fmaxf(tm0, __shfl_xor_sync(0xffffffffu, tm0, 2, 4));
        tm1 = fmaxf(tm1, __shfl_xor_sync(0xffffffffu, tm1, 1, 4));
        tm1 = fmaxf(tm1, __shfl_xor_sync(0xffffffffu, tm1, 2, 4));

        const float mn0 = fmaxf(m0, tm0), mn1 = fmaxf(m1, tm1);
        const float al0 = __expf(m0 - mn0), al1 = __expf(m1 - mn1);
        m0 = mn0; m1 = mn1;

        float ps0 = 0.f, ps1 = 0.f;
#pragma unroll
        for (int nf = 0; nf < 16; nf++) {
            sc[nf][0] = __expf(sc[nf][0] - mn0);
            sc[nf][1] = __expf(sc[nf][1] - mn0);
            sc[nf][2] = __expf(sc[nf][2] - mn1);
            sc[nf][3] = __expf(sc[nf][3] - mn1);
            ps0 += sc[nf][0] + sc[nf][1];
            ps1 += sc[nf][2] + sc[nf][3];
        }
        ps0 += __shfl_xor_sync(0xffffffffu, ps0, 1, 4);
        ps0 += __shfl_xor_sync(0xffffffffu, ps0, 2, 4);
        ps1 += __shfl_xor_sync(0xffffffffu, ps1, 1, 4);
        ps1 += __shfl_xor_sync(0xffffffffu, ps1, 2, 4);
        l0 = l0 * al0 + ps0;
        l1 = l1 * al1 + ps1;
#pragma unroll
        for (int i = 0; i < 8; i++) {
            o[i][0] *= al0; o[i][1] *= al0;
            o[i][2] *= al1; o[i][3] *= al1;
        }

        // ---- O += P V (P re-packed from sc; V via ldmatrix.trans) ----
#pragma unroll
        for (int j = 0; j < 8; j++) {
            const uint32_t ph0 = pack_hi(sc[2*j  ][0], sc[2*j  ][1]);
            const uint32_t ph1 = pack_hi(sc[2*j  ][2], sc[2*j  ][3]);
            const uint32_t ph2 = pack_hi(sc[2*j+1][0], sc[2*j+1][1]);
            const uint32_t ph3 = pack_hi(sc[2*j+1][2], sc[2*j+1][3]);
            const uint32_t pl0 = pack_lo(sc[2*j  ][0], sc[2*j  ][1]);
            const uint32_t pl1 = pack_lo(sc[2*j  ][2], sc[2*j  ][3]);
            const uint32_t pl2 = pack_lo(sc[2*j+1][0], sc[2*j+1][1]);
            const uint32_t pl3 = pack_lo(sc[2*j+1][2], sc[2*j+1][3]);
#pragma unroll
            for (int vx = 0; vx < 4; vx++) {
                uint32_t vh0,vh1,vh2,vh3, vl0,vl1,vl2,vl3;
                const uint32_t aV = lofV + j*2304 + vx*32;
                LDSM_X4_T(vh0,vh1,vh2,vh3, smbVhi + aV);
                LDSM_X4_T(vl0,vl1,vl2,vl3, smbVlo + aV);
                float* o0 = o[2*vx];
                float* o1 = o[2*vx+1];
                MMA_BF16(o0[0],o0[1],o0[2],o0[3], ph0,ph1,ph2,ph3, vh0,vh1);
                MMA_BF16(o0[0],o0[1],o0[2],o0[3], ph0,ph1,ph2,ph3, vl0,vl1);
                MMA_BF16(o0[0],o0[1],o0[2],o0[3], pl0,pl1,pl2,pl3, vh0,vh1);
                MMA_BF16(o1[0],o1[1],o1[2],o1[3], ph0,ph1,ph2,ph3, vh2,vh3);
                MMA_BF16(o1[0],o1[1],o1[2],o1[3], ph0,ph1,ph2,ph3, vl2,vl3);
                MMA_BF16(o1[0],o1[1],o1[2],o1[3], pl0,pl1,pl2,pl3, vh2,vh3);
            }
        }
    }

    // ---- epilogue: normalize, split to bf16 hi/lo, write [row][256] u32 ----
    const float i0 = 1.0f / l0, i1 = 1.0f / l1;
    const size_t gr  = (size_t)b*Nn + rq;
    const size_t gr8 = (size_t)b*Nn + rq8;
#pragma unroll
    for (int dnf = 0; dnf < 8; dnf++) {
        const int ucol = h*32 + dnf*4 + tig;
        {
            const float x = o[dnf][0]*i0, y = o[dnf][1]*i0;
            g_athi[gr*256 + ucol] = pack_hi(x, y);
            g_atlo[gr*256 + ucol] = pack_lo(x, y);
        }
        {
            const float x = o[dnf][2]*i1, y = o[dnf][3]*i1;
            g_athi[gr8*256 + ucol] = pack_hi(x, y);
            g_atlo[gr8*256 + ucol] = pack_lo(x, y);
        }
    }
}

// ---------------------------------------------------------------------------
// LayerNorm over last dim (512). One block (128 thr) per row.
// ---------------------------------------------------------------------------
__global__ __launch_bounds__(128) void ln_kernel(
    const float* __restrict__ gamma, const float* __restrict__ beta,
    float* __restrict__ out)
{
    const int row = blockIdx.x;
    const int t   = threadIdx.x;
    const float* y = g_y + (size_t)row * Dd;

    float4 v = *(const float4*)(y + t*4);
    float s  = v.x + v.y + v.z + v.w;
    float ss = v.x*v.x + v.y*v.y + v.z*v.z + v.w*v.w;
#pragma unroll
    for (int off = 16; off; off >>= 1) {
        s  += __shfl_xor_sync(0xffffffffu, s,  off);
        ss += __shfl_xor_sync(0xffffffffu, ss, off);
    }
    __shared__ float sbuf[8];
    const int w = t >> 5;
    if ((t & 31) == 0) { sbuf[w] = s; sbuf[4 + w] = ss; }
    __syncthreads();
    s  = sbuf[0] + sbuf[1] + sbuf[2] + sbuf[3];
    ss = sbuf[4] + sbuf[5] + sbuf[6] + sbuf[7];

    const float mean = s * (1.f/512.f);
    const float var  = ss * (1.f/512.f) - mean*mean;
    const float inv  = rsqrtf(var + 1e-5f);

    float4 g4 = *(const float4*)(gamma + t*4);
    float4 b4 = *(const float4*)(beta  + t*4);
    float4 r;
    r.x = (v.x - mean) * inv * g4.x + b4.x;
    r.y = (v.y - mean) * inv * g4.y + b4.y;
    r.z = (v.z - mean) * inv * g4.z + b4.z;
    r.w = (v.w - mean) * inv * g4.w + b4.w;
    *(float4*)(out + (size_t)row*Dd + t*4) = r;
}

// ---------------------------------------------------------------------------
extern "C" void kernel_launch(void* const* d_in, const int* in_sizes, int n_in,
                              void* d_out, int out_size)
{
    const float* X     = (const float*)d_in[0];
    const float* adj   = (const float*)d_in[1];
    const float* Wq    = (const float*)d_in[2];
    const float* bq    = (const float*)d_in[3];
    const float* Wk    = (const float*)d_in[4];
    const float* bk    = (const float*)d_in[5];
    const float* Wv    = (const float*)d_in[6];
    const float* bv    = (const float*)d_in[7];
    const float* Wo    = (const float*)d_in[8];
    const float* bo    = (const float*)d_in[9];
    const float* gamma = (const float*)d_in[10];
    const float* beta  = (const float*)d_in[11];

    uint32_t *xhi, *xlo, *whi, *wlo, *qhi, *qlo, *khi, *klo, *vhi, *vlo, *athi, *atlo;
    float *y;
    cudaGetSymbolAddress((void**)&xhi,  g_xhi);
    cudaGetSymbolAddress((void**)&xlo,  g_xlo);
    cudaGetSymbolAddress((void**)&whi,  g_whi);
    cudaGetSymbolAddress((void**)&wlo,  g_wlo);
    cudaGetSymbolAddress((void**)&qhi,  g_qhi);
    cudaGetSymbolAddress((void**)&qlo,  g_qlo);
    cudaGetSymbolAddress((void**)&khi,  g_khi);
    cudaGetSymbolAddress((void**)&klo,  g_klo);
    cudaGetSymbolAddress((void**)&vhi,  g_vhi);
    cudaGetSymbolAddress((void**)&vlo,  g_vlo);
    cudaGetSymbolAddress((void**)&athi, g_athi);
    cudaGetSymbolAddress((void**)&atlo, g_atlo);
    cudaGetSymbolAddress((void**)&y,    g_y);

    cudaFuncSetAttribute(gemm_tc,
                         cudaFuncAttributeMaxDynamicSharedMemorySize, GEMM_SMEM);
    cudaFuncSetAttribute(attn_kernel,
                         cudaFuncAttributeMaxDynamicSharedMemorySize, ATTN_SMEM);

    // split X and the 4 weights into bf16 hi/lo
    const int WU = 512*256;   // u32 per weight
    split_kernel<<<Mrows*512/4/256, 256>>>(X,  xhi, xlo, Mrows*512/4);
    split_kernel<<<512*512/4/256, 256>>>(Wq, whi + 0*WU, wlo + 0*WU, 512*512/4);
    split_kernel<<<512*512/4/256, 256>>>(Wk, whi + 1*WU, wlo + 1*WU, 512*512/4);
    split_kernel<<<512*512/4/256, 256>>>(Wv, whi + 2*WU, wlo + 2*WU, 512*512/4);
    split_kernel<<<512*512/4/256, 256>>>(Wo, whi + 3*WU, wlo + 3*WU, 512*512/4);

    dim3 ggrid(Mrows/128, Dd/128);
    gemm_tc<<<ggrid, 256, GEMM_SMEM>>>(xhi, xlo, whi + 0*WU, wlo + 0*WU, bq,
                                       nullptr, nullptr, qhi, qlo, 0);
    gemm_tc<<<ggrid, 256, GEMM_SMEM>>>(xhi, xlo, whi + 1*WU, wlo + 1*WU, bk,
                                       nullptr, nullptr, khi, klo, 0);
    gemm_tc<<<ggrid, 256, GEMM_SMEM>>>(xhi, xlo, whi + 2*WU, wlo + 2*WU, bv,
                                       nullptr, nullptr, vhi, vlo, 0);

    attn_kernel<<<dim3(Nn/128, Hh, Bsz), 256, ATTN_SMEM>>>(adj);

    gemm_tc<<<ggrid, 256, GEMM_SMEM>>>(athi, atlo, whi + 3*WU, wlo + 3*WU, bo,
                                       X, y, nullptr, nullptr, 1);

    ln_kernel<<<Mrows, 128>>>(gamma, beta, (float*)d_out);
}

// round 6
// speedup vs baseline: 2.1806x; 1.0656x over previous
#include <cuda_runtime.h>
#include <cuda_bf16.h>
#include <math.h>
#include <stdint.h>

#define Bsz 8
#define Nn  1024
#define Dd  512
#define Hh  8
#define HD  64
#define Mrows (Bsz*Nn)

// ---------------- scratch (device globals) ----------------
__device__ uint32_t g_xhi[Mrows*256], g_xlo[Mrows*256];        // X split  [row][256]
__device__ uint32_t g_whi[4*512*256], g_wlo[4*512*256];        // 4 weights [w][row][256]
__device__ uint32_t g_qhi[Mrows*32*Hh], g_qlo[Mrows*32*Hh];    // [B,H,N][32]
__device__ uint32_t g_khi[Mrows*32*Hh], g_klo[Mrows*32*Hh];
__device__ uint32_t g_vhi[Mrows*32*Hh], g_vlo[Mrows*32*Hh];
__device__ uint32_t g_athi[Mrows*256], g_atlo[Mrows*256];      // attn out split [row][256]
__device__ float    g_y[(size_t)Mrows*Dd];

// ---------------- helpers ----------------
__device__ __forceinline__ uint32_t smem_u32(const void* p) {
    uint32_t a;
    asm("{ .reg .u64 t; cvta.to.shared.u64 t, %1; cvt.u32.u64 %0, t; }" : "=r"(a) : "l"(p));
    return a;
}
__device__ __forceinline__ float ex2f(float x) {
    float r;
    asm("ex2.approx.ftz.f32 %0, %1;" : "=f"(r) : "f"(x));
    return r;
}
#define MMA_BF16(c0,c1,c2,c3, a0,a1,a2,a3, b0,b1) \
    asm volatile("mma.sync.aligned.m16n8k16.row.col.f32.bf16.bf16.f32 " \
        "{%0,%1,%2,%3},{%4,%5,%6,%7},{%8,%9},{%0,%1,%2,%3};" \
        : "+f"(c0),"+f"(c1),"+f"(c2),"+f"(c3) \
        : "r"(a0),"r"(a1),"r"(a2),"r"(a3),"r"(b0),"r"(b1))
#define LDSM_X4(r0,r1,r2,r3, a) \
    asm volatile("ldmatrix.sync.aligned.m8n8.x4.shared.b16 {%0,%1,%2,%3}, [%4];" \
        : "=r"(r0),"=r"(r1),"=r"(r2),"=r"(r3) : "r"(a))
#define LDSM_X4_T(r0,r1,r2,r3, a) \
    asm volatile("ldmatrix.sync.aligned.m8n8.x4.trans.shared.b16 {%0,%1,%2,%3}, [%4];" \
        : "=r"(r0),"=r"(r1),"=r"(r2),"=r"(r3) : "r"(a))

__device__ __forceinline__ uint32_t pack_hi(float x, float y) {
    __nv_bfloat162 p;
    p.x = __float2bfloat16(x);
    p.y = __float2bfloat16(y);
    return *(uint32_t*)&p;
}
__device__ __forceinline__ uint32_t pack_lo(float x, float y) {
    __nv_bfloat16 hx = __float2bfloat16(x);
    __nv_bfloat16 hy = __float2bfloat16(y);
    __nv_bfloat162 p;
    p.x = __float2bfloat16(x - __bfloat162float(hx));
    p.y = __float2bfloat16(y - __bfloat162float(hy));
    return *(uint32_t*)&p;
}

// ---------------- split converts ----------------
__global__ __launch_bounds__(256) void split_kernel(
    const float* __restrict__ in, uint32_t* __restrict__ hi,
    uint32_t* __restrict__ lo, int n4)
{
    int i = blockIdx.x * 256 + threadIdx.x;
    if (i < n4) {
        float4 v = ((const float4*)in)[i];
        uint2 h, l;
        h.x = pack_hi(v.x, v.y); h.y = pack_hi(v.z, v.w);
        l.x = pack_lo(v.x, v.y); l.y = pack_lo(v.z, v.w);
        ((uint2*)hi)[i] = h;
        ((uint2*)lo)[i] = l;
    }
}

// 4 weights in one launch (grid.y selects which)
__global__ __launch_bounds__(256) void split4_kernel(
    const float* __restrict__ w0, const float* __restrict__ w1,
    const float* __restrict__ w2, const float* __restrict__ w3,
    uint32_t* __restrict__ hi, uint32_t* __restrict__ lo)
{
    const int wsel = blockIdx.y;
    const float* in = (wsel == 0) ? w0 : (wsel == 1) ? w1 : (wsel == 2) ? w2 : w3;
    const int i = blockIdx.x * 256 + threadIdx.x;       // < 65536
    const size_t off = (size_t)wsel * 512 * 256;
    float4 v = ((const float4*)in)[i];
    uint2 h, l;
    h.x = pack_hi(v.x, v.y); h.y = pack_hi(v.z, v.w);
    l.x = pack_lo(v.x, v.y); l.y = pack_lo(v.z, v.w);
    ((uint2*)(hi + off))[i] = h;
    ((uint2*)(lo + off))[i] = l;
}

// ===========================================================================
// bf16-split GEMM (pre-split inputs). CTA 128x128, 8 warps (2x4), K-stage 64.
// mode 0: write split u32 into [B,H,N][32].  mode 1: fp32 + bias + resid.
// ===========================================================================
#define APAD2 36
#define TILE_U32 (128*APAD2)
#define GEMM_SMEM (2*4*TILE_U32*4)    // 147456 bytes

__device__ __forceinline__ void gfill(
    uint32_t* smu, int stage,
    const uint32_t* __restrict__ Ahi, const uint32_t* __restrict__ Alo,
    const uint32_t* __restrict__ Bhi, const uint32_t* __restrict__ Blo,
    int row0, int col0, int k0u, int t)
{
    const int r = t >> 1, c0 = (t & 1) * 16;
    uint32_t* d = smu + stage * 4 * TILE_U32;
    const uint32_t* s0 = Ahi + (size_t)(row0 + r) * 256 + k0u + c0;
    const uint32_t* s1 = Alo + (size_t)(row0 + r) * 256 + k0u + c0;
    const uint32_t* s2 = Bhi + (size_t)(col0 + r) * 256 + k0u + c0;
    const uint32_t* s3 = Blo + (size_t)(col0 + r) * 256 + k0u + c0;
    uint32_t* dd = d + r * APAD2 + c0;
#pragma unroll
    for (int u = 0; u < 4; u++) {
        ((uint4*)(dd             ))[u] = ((const uint4*)s0)[u];
        ((uint4*)(dd + TILE_U32  ))[u] = ((const uint4*)s1)[u];
        ((uint4*)(dd + 2*TILE_U32))[u] = ((const uint4*)s2)[u];
        ((uint4*)(dd + 3*TILE_U32))[u] = ((const uint4*)s3)[u];
    }
}

__global__ __launch_bounds__(256, 1) void gemm_tc(
    const uint32_t* __restrict__ Ahi, const uint32_t* __restrict__ Alo,
    const uint32_t* __restrict__ Bwhi, const uint32_t* __restrict__ Bwlo,
    const float* __restrict__ bias, const float* __restrict__ resid,
    float* __restrict__ outf, uint32_t* __restrict__ outhi,
    uint32_t* __restrict__ outlo, int mode)
{
    extern __shared__ uint32_t smu[];
    const int t = threadIdx.x;
    const int lane = t & 31, wid = t >> 5;
    const int row0 = blockIdx.x * 128, col0 = blockIdx.y * 128;
    const int wm = wid & 1, wn = wid >> 1;
    const int g = lane >> 2, tig = lane & 3;

    float acc[4][4][4];
#pragma unroll
    for (int mt = 0; mt < 4; mt++)
#pragma unroll
        for (int nt = 0; nt < 4; nt++)
#pragma unroll
            for (int e = 0; e < 4; e++) acc[mt][nt][e] = 0.f;

    gfill(smu, 0, Ahi, Alo, Bwhi, Bwlo, row0, col0, 0, t);
    __syncthreads();

    for (int kt = 0; kt < 8; kt++) {
        if (kt < 7) gfill(smu, (kt + 1) & 1, Ahi, Alo, Bwhi, Bwlo, row0, col0, (kt + 1) * 32, t);

        const uint32_t* base = smu + (kt & 1) * 4 * TILE_U32;
        const uint32_t* sAhi = base;
        const uint32_t* sAlo = base + TILE_U32;
        const uint32_t* sBhi = base + 2*TILE_U32;
        const uint32_t* sBlo = base + 3*TILE_U32;

#pragma unroll
        for (int ks = 0; ks < 4; ks++) {
            const int kb = ks * 8;
            uint32_t ah[4][4], al[4][4], bh[4][2], bl[4][2];
#pragma unroll
            for (int mt = 0; mt < 4; mt++) {
                const int r0 = wm*64 + mt*16 + g;
                ah[mt][0] = sAhi[ r0     *APAD2 + kb + tig];
                ah[mt][1] = sAhi[(r0 + 8)*APAD2 + kb + tig];
                ah[mt][2] = sAhi[ r0     *APAD2 + kb + tig + 4];
                ah[mt][3] = sAhi[(r0 + 8)*APAD2 + kb + tig + 4];
                al[mt][0] = sAlo[ r0     *APAD2 + kb + tig];
                al[mt][1] = sAlo[(r0 + 8)*APAD2 + kb + tig];
                al[mt][2] = sAlo[ r0     *APAD2 + kb + tig + 4];
                al[mt][3] = sAlo[(r0 + 8)*APAD2 + kb + tig + 4];
            }
#pragma unroll
            for (int nt = 0; nt < 4; nt++) {
                const int n0 = wn*32 + nt*8 + g;
                bh[nt][0] = sBhi[n0*APAD2 + kb + tig];
                bh[nt][1] = sBhi[n0*APAD2 + kb + tig + 4];
                bl[nt][0] = sBlo[n0*APAD2 + kb + tig];
                bl[nt][1] = sBlo[n0*APAD2 + kb + tig + 4];
            }
#pragma unroll
            for (int mt = 0; mt < 4; mt++)
#pragma unroll
                for (int nt = 0; nt < 4; nt++) {
                    MMA_BF16(acc[mt][nt][0],acc[mt][nt][1],acc[mt][nt][2],acc[mt][nt][3],
                             ah[mt][0],ah[mt][1],ah[mt][2],ah[mt][3], bh[nt][0],bh[nt][1]);
                    MMA_BF16(acc[mt][nt][0],acc[mt][nt][1],acc[mt][nt][2],acc[mt][nt][3],
                             ah[mt][0],ah[mt][1],ah[mt][2],ah[mt][3], bl[nt][0],bl[nt][1]);
                    MMA_BF16(acc[mt][nt][0],acc[mt][nt][1],acc[mt][nt][2],acc[mt][nt][3],
                             al[mt][0],al[mt][1],al[mt][2],al[mt][3], bh[nt][0],bh[nt][1]);
                }
        }
        __syncthreads();
    }

#pragma unroll
    for (int mt = 0; mt < 4; mt++) {
#pragma unroll
        for (int nt = 0; nt < 4; nt++) {
            const int gc = col0 + wn*32 + nt*8 + tig*2;
            const float b0 = bias[gc], b1 = bias[gc+1];
            const int ra = row0 + wm*64 + mt*16 + g;
            const int rb = ra + 8;
            if (mode == 0) {
                const int h = gc >> 6, ucol = (gc >> 1) & 31;
                {
                    const int bi = ra >> 10, ni = ra & 1023;
                    const float x = acc[mt][nt][0] + b0, y = acc[mt][nt][1] + b1;
                    const size_t o = ((size_t)(bi*Hh + h)*Nn + ni)*32 + ucol;
                    outhi[o] = pack_hi(x, y);  outlo[o] = pack_lo(x, y);
                }
                {
                    const int bi = rb >> 10, ni = rb & 1023;
                    const float x = acc[mt][nt][2] + b0, y = acc[mt][nt][3] + b1;
                    const size_t o = ((size_t)(bi*Hh + h)*Nn + ni)*32 + ucol;
                    outhi[o] = pack_hi(x, y);  outlo[o] = pack_lo(x, y);
                }
            } else {
                {
                    const size_t off = (size_t)ra * Dd + gc;
                    float2 x = *(const float2*)(resid + off);
                    float2 r; r.x = acc[mt][nt][0] + b0 + x.x; r.y = acc[mt][nt][1] + b1 + x.y;
                    *(float2*)(outf + off) = r;
                }
                {
                    const size_t off = (size_t)rb * Dd + gc;
                    float2 x = *(const float2*)(resid + off);
                    float2 r; r.x = acc[mt][nt][2] + b0 + x.x; r.y = acc[mt][nt][3] + b1 + x.y;
                    *(float2*)(outf + off) = r;
                }
            }
        }
    }
}

// ===========================================================================
// Tensor-core flash attention, FIXED-MAX softmax (scores provably ~|s|<2).
// CTA = 128q x (b,h); 8 warps, warp = 16q x 128k.
// e = 2^(s*scale*log2e*adj); l accumulates; no max tracking, no rescale.
// ===========================================================================
#define ASTRIDE 144                    // bytes per smem row (36 u32)
#define AT_TILE_U32 (128*36)           // one K/V tile
#define ATTN_SMEM (4*AT_TILE_U32*4)    // 73728 bytes

__global__ __launch_bounds__(256, 1) void attn_kernel(const float* __restrict__ adj)
{
    extern __shared__ uint32_t smu[];
    const uint32_t smb = smem_u32(smu);
    const int t = threadIdx.x;
    const int lane = t & 31, wid = t >> 5;
    const int g = lane >> 2, tig = lane & 3;
    const int lm = lane >> 3, lr8 = lane & 7;
    const int q0 = blockIdx.x * 128;
    const int h  = blockIdx.y;
    const int b  = blockIdx.z;

    const size_t hbase = (size_t)(b*Hh + h) * Nn * 32;
    const uint32_t* Qhi = g_qhi + hbase;
    const uint32_t* Qlo = g_qlo + hbase;
    const uint32_t* Khi = g_khi + hbase;
    const uint32_t* Klo = g_klo + hbase;
    const uint32_t* Vhi = g_vhi + hbase;
    const uint32_t* Vlo = g_vlo + hbase;

    const uint32_t smbKhi = smb;
    const uint32_t smbKlo = smb + 1*AT_TILE_U32*4;
    const uint32_t smbVhi = smb + 2*AT_TILE_U32*4;
    const uint32_t smbVlo = smb + 3*AT_TILE_U32*4;

    const int lofK = ((lm >> 1)*8 + lr8) * ASTRIDE + (lm & 1) * 16;
    const int lofV = ((lm & 1)*8 + lr8) * ASTRIDE + (lm >> 1) * 16;

    const int rq  = q0 + wid*16 + g;
    const int rq8 = rq + 8;
    uint32_t qh[4][4], ql[4][4];
#pragma unroll
    for (int ks = 0; ks < 4; ks++) {
        const int c = ks*8 + tig;
        qh[ks][0] = Qhi[(size_t)rq *32 + c];     qh[ks][1] = Qhi[(size_t)rq8*32 + c];
        qh[ks][2] = Qhi[(size_t)rq *32 + c + 4]; qh[ks][3] = Qhi[(size_t)rq8*32 + c + 4];
        ql[ks][0] = Qlo[(size_t)rq *32 + c];     ql[ks][1] = Qlo[(size_t)rq8*32 + c];
        ql[ks][2] = Qlo[(size_t)rq *32 + c + 4]; ql[ks][3] = Qlo[(size_t)rq8*32 + c + 4];
    }

    float o[8][4];
#pragma unroll
    for (int i = 0; i < 8; i++)
#pragma unroll
        for (int e = 0; e < 4; e++) o[i][e] = 0.f;
    float l0 = 0.f, l1 = 0.f;
    const float C = 0.125f * 1.44269504088896f;   // scale * log2(e)

    const int fr = t >> 1, fc = (t & 1) * 16;

    for (int kt = 0; kt < 8; kt++) {
        const int k0 = kt * 128;
        __syncthreads();
        {
            const size_t gsrc = (size_t)(k0 + fr) * 32 + fc;
            uint32_t* d = smu + fr*36 + fc;
#pragma unroll
            for (int u = 0; u < 4; u++) {
                ((uint4*)(d                ))[u] = ((const uint4*)(Khi + gsrc))[u];
                ((uint4*)(d +   AT_TILE_U32))[u] = ((const uint4*)(Klo + gsrc))[u];
                ((uint4*)(d + 2*AT_TILE_U32))[u] = ((const uint4*)(Vhi + gsrc))[u];
                ((uint4*)(d + 3*AT_TILE_U32))[u] = ((const uint4*)(Vlo + gsrc))[u];
            }
        }
        __syncthreads();

        // ---- S = Q K^T (3 split passes) ----
        float sc[16][4];
#pragma unroll
        for (int i = 0; i < 16; i++)
#pragma unroll
            for (int e = 0; e < 4; e++) sc[i][e] = 0.f;

#pragma unroll
        for (int ks = 0; ks < 4; ks++) {
#pragma unroll
            for (int nfp = 0; nfp < 8; nfp++) {
                uint32_t kh0,kh1,kh2,kh3, kl0,kl1,kl2,kl3;
                const uint32_t aK = lofK + nfp*2304 + ks*32;
                LDSM_X4(kh0,kh1,kh2,kh3, smbKhi + aK);
                LDSM_X4(kl0,kl1,kl2,kl3, smbKlo + aK);
                float* s0 = sc[2*nfp];
                float* s1 = sc[2*nfp+1];
                MMA_BF16(s0[0],s0[1],s0[2],s0[3], qh[ks][0],qh[ks][1],qh[ks][2],qh[ks][3], kh0,kh1);
                MMA_BF16(s0[0],s0[1],s0[2],s0[3], qh[ks][0],qh[ks][1],qh[ks][2],qh[ks][3], kl0,kl1);
                MMA_BF16(s0[0],s0[1],s0[2],s0[3], ql[ks][0],ql[ks][1],ql[ks][2],ql[ks][3], kh0,kh1);
                MMA_BF16(s1[0],s1[1],s1[2],s1[3], qh[ks][0],qh[ks][1],qh[ks][2],qh[ks][3], kh2,kh3);
                MMA_BF16(s1[0],s1[1],s1[2],s1[3], qh[ks][0],qh[ks][1],qh[ks][2],qh[ks][3], kl2,kl3);
                MMA_BF16(s1[0],s1[1],s1[2],s1[3], ql[ks][0],ql[ks][1],ql[ks][2],ql[ks][3], kh2,kh3);
            }
        }

        // ---- mask + exp (fixed max) + sum ----
        const float* arow0 = adj + ((size_t)b*Nn + rq )*Nn + k0 + 2*tig;
        const float* arow1 = adj + ((size_t)b*Nn + rq8)*Nn + k0 + 2*tig;
        float ps0 = 0.f, ps1 = 0.f;
#pragma unroll
        for (int nf = 0; nf < 16; nf++) {
            float2 a0 = *(const float2*)(arow0 + nf*8);
            float2 a1 = *(const float2*)(arow1 + nf*8);
            sc[nf][0] = ex2f(sc[nf][0] * C * a0.x);
            sc[nf][1] = ex2f(sc[nf][1] * C * a0.y);
            sc[nf][2] = ex2f(sc[nf][2] * C * a1.x);
            sc[nf][3] = ex2f(sc[nf][3] * C * a1.y);
            ps0 += sc[nf][0] + sc[nf][1];
            ps1 += sc[nf][2] + sc[nf][3];
        }
        l0 += ps0;
        l1 += ps1;

        // ---- O += P V ----
#pragma unroll
        for (int j = 0; j < 8; j++) {
            const uint32_t ph0 = pack_hi(sc[2*j  ][0], sc[2*j  ][1]);
            const uint32_t ph1 = pack_hi(sc[2*j  ][2], sc[2*j  ][3]);
            const uint32_t ph2 = pack_hi(sc[2*j+1][0], sc[2*j+1][1]);
            const uint32_t ph3 = pack_hi(sc[2*j+1][2], sc[2*j+1][3]);
            const uint32_t pl0 = pack_lo(sc[2*j  ][0], sc[2*j  ][1]);
            const uint32_t pl1 = pack_lo(sc[2*j  ][2], sc[2*j  ][3]);
            const uint32_t pl2 = pack_lo(sc[2*j+1][0], sc[2*j+1][1]);
            const uint32_t pl3 = pack_lo(sc[2*j+1][2], sc[2*j+1][3]);
#pragma unroll
            for (int vx = 0; vx < 4; vx++) {
                uint32_t vh0,vh1,vh2,vh3, vl0,vl1,vl2,vl3;
                const uint32_t aV = lofV + j*2304 + vx*32;
                LDSM_X4_T(vh0,vh1,vh2,vh3, smbVhi + aV);
                LDSM_X4_T(vl0,vl1,vl2,vl3, smbVlo + aV);
                float* o0 = o[2*vx];
                float* o1 = o[2*vx+1];
                MMA_BF16(o0[0],o0[1],o0[2],o0[3], ph0,ph1,ph2,ph3, vh0,vh1);
                MMA_BF16(o0[0],o0[1],o0[2],o0[3], ph0,ph1,ph2,ph3, vl0,vl1);
                MMA_BF16(o0[0],o0[1],o0[2],o0[3], pl0,pl1,pl2,pl3, vh0,vh1);
                MMA_BF16(o1[0],o1[1],o1[2],o1[3], ph0,ph1,ph2,ph3, vh2,vh3);
                MMA_BF16(o1[0],o1[1],o1[2],o1[3], ph0,ph1,ph2,ph3, vl2,vl3);
                MMA_BF16(o1[0],o1[1],o1[2],o1[3], pl0,pl1,pl2,pl3, vh2,vh3);
            }
        }
    }

    // in-quad reduce of l (lanes 4g..4g+3 hold partial sums over key subsets)
    l0 += __shfl_xor_sync(0xffffffffu, l0, 1, 4);
    l0 += __shfl_xor_sync(0xffffffffu, l0, 2, 4);
    l1 += __shfl_xor_sync(0xffffffffu, l1, 1, 4);
    l1 += __shfl_xor_sync(0xffffffffu, l1, 2, 4);

    const float i0 = 1.0f / l0, i1 = 1.0f / l1;
    const size_t gr  = (size_t)b*Nn + rq;
    const size_t gr8 = (size_t)b*Nn + rq8;
#pragma unroll
    for (int dnf = 0; dnf < 8; dnf++) {
        const int ucol = h*32 + dnf*4 + tig;
        {
            const float x = o[dnf][0]*i0, y = o[dnf][1]*i0;
            g_athi[gr*256 + ucol] = pack_hi(x, y);
            g_atlo[gr*256 + ucol] = pack_lo(x, y);
        }
        {
            const float x = o[dnf][2]*i1, y = o[dnf][3]*i1;
            g_athi[gr8*256 + ucol] = pack_hi(x, y);
            g_atlo[gr8*256 + ucol] = pack_lo(x, y);
        }
    }
}

// ---------------------------------------------------------------------------
// LayerNorm over last dim (512). One block (128 thr) per row.
// ---------------------------------------------------------------------------
__global__ __launch_bounds__(128) void ln_kernel(
    const float* __restrict__ gamma, const float* __restrict__ beta,
    float* __restrict__ out)
{
    const int row = blockIdx.x;
    const int t   = threadIdx.x;
    const float* y = g_y + (size_t)row * Dd;

    float4 v = *(const float4*)(y + t*4);
    float s  = v.x + v.y + v.z + v.w;
    float ss = v.x*v.x + v.y*v.y + v.z*v.z + v.w*v.w;
#pragma unroll
    for (int off = 16; off; off >>= 1) {
        s  += __shfl_xor_sync(0xffffffffu, s,  off);
        ss += __shfl_xor_sync(0xffffffffu, ss, off);
    }
    __shared__ float sbuf[8];
    const int w = t >> 5;
    if ((t & 31) == 0) { sbuf[w] = s; sbuf[4 + w] = ss; }
    __syncthreads();
    s  = sbuf[0] + sbuf[1] + sbuf[2] + sbuf[3];
    ss = sbuf[4] + sbuf[5] + sbuf[6] + sbuf[7];

    const float mean = s * (1.f/512.f);
    const float var  = ss * (1.f/512.f) - mean*mean;
    const float inv  = rsqrtf(var + 1e-5f);

    float4 g4 = *(const float4*)(gamma + t*4);
    float4 b4 = *(const float4*)(beta  + t*4);
    float4 r;
    r.x = (v.x - mean) * inv * g4.x + b4.x;
    r.y = (v.y - mean) * inv * g4.y + b4.y;
    r.z = (v.z - mean) * inv * g4.z + b4.z;
    r.w = (v.w - mean) * inv * g4.w + b4.w;
    *(float4*)(out + (size_t)row*Dd + t*4) = r;
}

// ---------------------------------------------------------------------------
extern "C" void kernel_launch(void* const* d_in, const int* in_sizes, int n_in,
                              void* d_out, int out_size)
{
    const float* X     = (const float*)d_in[0];
    const float* adj   = (const float*)d_in[1];
    const float* Wq    = (const float*)d_in[2];
    const float* bq    = (const float*)d_in[3];
    const float* Wk    = (const float*)d_in[4];
    const float* bk    = (const float*)d_in[5];
    const float* Wv    = (const float*)d_in[6];
    const float* bv    = (const float*)d_in[7];
    const float* Wo    = (const float*)d_in[8];
    const float* bo    = (const float*)d_in[9];
    const float* gamma = (const float*)d_in[10];
    const float* beta  = (const float*)d_in[11];

    uint32_t *xhi, *xlo, *whi, *wlo, *qhi, *qlo, *khi, *klo, *vhi, *vlo, *athi, *atlo;
    float *y;
    cudaGetSymbolAddress((void**)&xhi,  g_xhi);
    cudaGetSymbolAddress((void**)&xlo,  g_xlo);
    cudaGetSymbolAddress((void**)&whi,  g_whi);
    cudaGetSymbolAddress((void**)&wlo,  g_wlo);
    cudaGetSymbolAddress((void**)&qhi,  g_qhi);
    cudaGetSymbolAddress((void**)&qlo,  g_qlo);
    cudaGetSymbolAddress((void**)&khi,  g_khi);
    cudaGetSymbolAddress((void**)&klo,  g_klo);
    cudaGetSymbolAddress((void**)&vhi,  g_vhi);
    cudaGetSymbolAddress((void**)&vlo,  g_vlo);
    cudaGetSymbolAddress((void**)&athi, g_athi);
    cudaGetSymbolAddress((void**)&atlo, g_atlo);
    cudaGetSymbolAddress((void**)&y,    g_y);

    cudaFuncSetAttribute(gemm_tc,
                         cudaFuncAttributeMaxDynamicSharedMemorySize, GEMM_SMEM);
    cudaFuncSetAttribute(attn_kernel,
                         cudaFuncAttributeMaxDynamicSharedMemorySize, ATTN_SMEM);

    const int WU = 512*256;   // u32 per weight
    split_kernel<<<Mrows*512/4/256, 256>>>(X, xhi, xlo, Mrows*512/4);
    split4_kernel<<<dim3(256, 4), 256>>>(Wq, Wk, Wv, Wo, whi, wlo);

    dim3 ggrid(Mrows/128, Dd/128);
    gemm_tc<<<ggrid, 256, GEMM_SMEM>>>(xhi, xlo, whi + 0*WU, wlo + 0*WU, bq,
                                       nullptr, nullptr, qhi, qlo, 0);
    gemm_tc<<<ggrid, 256, GEMM_SMEM>>>(xhi, xlo, whi + 1*WU, wlo + 1*WU, bk,
                                       nullptr, nullptr, khi, klo, 0);
    gemm_tc<<<ggrid, 256, GEMM_SMEM>>>(xhi, xlo, whi + 2*WU, wlo + 2*WU, bv,
                                       nullptr, nullptr, vhi, vlo, 0);

    attn_kernel<<<dim3(Nn/128, Hh, Bsz), 256, ATTN_SMEM>>>(adj);

    gemm_tc<<<ggrid, 256, GEMM_SMEM>>>(athi, atlo, whi + 3*WU, wlo + 3*WU, bo,
                                       X, y, nullptr, nullptr, 1);

    ln_kernel<<<Mrows, 128>>>(gamma, beta, (float*)d_out);
}